// round 5
// baseline (speedup 1.0000x reference)
#include <cuda_runtime.h>
#include <cuda_bf16.h>
#include <cstdint>

#define BQ   1024
#define SEQ  96
#define IN   128
#define HH   1024
#define G4   4096
#define KT   1152   // IN + HH
#define HOR  24
#define OUTD 128

// ---------------- device scratch (static, no allocs) ----------------
__device__ float g_xT[SEQ * BQ * IN];    // time-major x, tf32-rounded
__device__ float g_We[G4 * KT];          // [W_ih_e | W_hh_e], tf32
__device__ float g_Wd[G4 * KT];          // [W_ih_d | W_hh_d], tf32
__device__ float g_Wfc[HH * HH];
__device__ float g_Wfcc[HH * HH];
__device__ float g_Wout[OUTD * HH];
__device__ float g_be[G4];
__device__ float g_bd[G4];
__device__ float g_hA[BQ * HH];
__device__ float g_hB[BQ * HH];
__device__ float g_c[BQ * HH];
__device__ float g_hdA[BQ * HH];
__device__ float g_hdB[BQ * HH];
__device__ float g_cd[BQ * HH];
__device__ float g_out[BQ * OUTD];

__device__ __forceinline__ float to_tf32(float x) {
    uint32_t r;
    asm("cvt.rna.tf32.f32 %0, %1;" : "=r"(r) : "f"(x));
    return __uint_as_float(r);
}

__device__ __forceinline__ void mma8(float* c, const uint32_t* a, const uint32_t* b) {
    asm volatile(
        "mma.sync.aligned.m16n8k8.row.col.f32.tf32.tf32.f32 "
        "{%0,%1,%2,%3}, {%4,%5,%6,%7}, {%8,%9}, {%0,%1,%2,%3};"
        : "+f"(c[0]), "+f"(c[1]), "+f"(c[2]), "+f"(c[3])
        : "r"(a[0]), "r"(a[1]), "r"(a[2]), "r"(a[3]), "r"(b[0]), "r"(b[1]));
}

// ================= fused GEMM + LSTM cell step =================
// Block tile: 128 rows x (4 gates x 64 cols). grid = (8, 16).
// gates = [Ax | Ah] @ W^T + bias ; LSTM update; c in-place fp32; h_out tf32.
__global__ void __launch_bounds__(256, 1)
lstm_step(const float* __restrict__ Ax,   // [BQ][IN] (x_t slice or decoder out)
          const float* __restrict__ Ah,   // [BQ][HH]
          const float* __restrict__ W,    // [G4][KT]
          const float* __restrict__ bias, // [G4]  (b_ih + b_hh)
          float* __restrict__ c_io,       // [BQ][HH] fp32, in-place
          float* __restrict__ h_out)      // [BQ][HH] tf32-rounded fp32
{
    extern __shared__ float sm[];
    float* As = sm;              // [128][36]
    float* Bs = sm + 128 * 36;   // [256][36]

    const int m0 = blockIdx.x * 128;
    const int n0 = blockIdx.y * 64;
    const int tid = threadIdx.x;
    const int warp = tid >> 5, lane = tid & 31;
    const int wm = warp >> 2, wn = warp & 3;       // 2 x 4 warps; wn == gate
    const int grp = lane >> 2, tig = lane & 3;

    float acc[4][8][4];
#pragma unroll
    for (int i = 0; i < 4; i++)
#pragma unroll
        for (int j = 0; j < 8; j++)
#pragma unroll
            for (int k = 0; k < 4; k++) acc[i][j][k] = 0.f;

    for (int kt = 0; kt < KT / 32; kt++) {
        const int k0 = kt * 32;
        __syncthreads();
        // stage A tile 128x32 (float4)
#pragma unroll
        for (int it = 0; it < 4; it++) {
            int idx = tid + it * 256;
            int r = idx >> 3, v = idx & 7;
            const float* src = (k0 < IN)
                ? (Ax + (m0 + r) * IN + k0 + v * 4)
                : (Ah + (m0 + r) * HH + (k0 - IN) + v * 4);
            *(float4*)(As + r * 36 + v * 4) = *(const float4*)src;
        }
        // stage B tile 256x32: rows = 4 gate chunks of 64 W-rows
#pragma unroll
        for (int it = 0; it < 8; it++) {
            int idx = tid + it * 256;
            int r = idx >> 3, v = idx & 7;
            int gate = r >> 6, jj = r & 63;
            const float* src = W + (size_t)(gate * HH + n0 + jj) * KT + k0 + v * 4;
            *(float4*)(Bs + r * 36 + v * 4) = *(const float4*)src;
        }
        __syncthreads();
#pragma unroll
        for (int ks = 0; ks < 4; ks++) {
            uint32_t af[4][4], bf[8][2];
#pragma unroll
            for (int ms = 0; ms < 4; ms++) {
                int r = wm * 64 + ms * 16 + grp;
                af[ms][0] = __float_as_uint(As[r * 36 + ks * 8 + tig]);
                af[ms][1] = __float_as_uint(As[(r + 8) * 36 + ks * 8 + tig]);
                af[ms][2] = __float_as_uint(As[r * 36 + ks * 8 + tig + 4]);
                af[ms][3] = __float_as_uint(As[(r + 8) * 36 + ks * 8 + tig + 4]);
            }
#pragma unroll
            for (int ns = 0; ns < 8; ns++) {
                int nb = wn * 64 + ns * 8 + grp;
                bf[ns][0] = __float_as_uint(Bs[nb * 36 + ks * 8 + tig]);
                bf[ns][1] = __float_as_uint(Bs[nb * 36 + ks * 8 + tig + 4]);
            }
#pragma unroll
            for (int ms = 0; ms < 4; ms++)
#pragma unroll
                for (int ns = 0; ns < 8; ns++)
                    mma8(acc[ms][ns], af[ms], bf[ns]);
        }
    }

    // -------- epilogue: gather all 4 gates per (b,j) via smem --------
    __syncthreads();
    float* Cs = sm;  // [128][264] fp32, reuses staging
#pragma unroll
    for (int ms = 0; ms < 4; ms++) {
#pragma unroll
        for (int ns = 0; ns < 8; ns++) {
            int r = wm * 64 + ms * 16 + grp;
            int cc = wn * 64 + ns * 8 + tig * 2;
            Cs[r * 264 + cc]           = acc[ms][ns][0];
            Cs[r * 264 + cc + 1]       = acc[ms][ns][1];
            Cs[(r + 8) * 264 + cc]     = acc[ms][ns][2];
            Cs[(r + 8) * 264 + cc + 1] = acc[ms][ns][3];
        }
    }
    __syncthreads();
    for (int e = tid; e < 128 * 64; e += 256) {
        int r = e >> 6, j = e & 63;
        int col = n0 + j;
        int b = m0 + r;
        float iv = Cs[r * 264 + j]       + bias[col];
        float fv = Cs[r * 264 + 64 + j]  + bias[HH + col];
        float gv = Cs[r * 264 + 128 + j] + bias[2 * HH + col];
        float ov = Cs[r * 264 + 192 + j] + bias[3 * HH + col];
        float co = c_io[b * HH + col];
        float si = 1.f / (1.f + __expf(-iv));
        float sf = 1.f / (1.f + __expf(-fv));
        float so = 1.f / (1.f + __expf(-ov));
        float cn = sf * co + si * tanhf(gv);
        float hn = so * tanhf(cn);
        c_io[b * HH + col] = cn;
        h_out[b * HH + col] = to_tf32(hn);
    }
}

// ================= generic linear: C = A @ W^T + bias =================
// A: [1024][1024] tf32, W: [N][1024] tf32. Block BM x 128, 256 threads.
template <int BM>
__global__ void __launch_bounds__(256)
linear_k(const float* __restrict__ A, const float* __restrict__ W,
         const float* __restrict__ bias,
         float* __restrict__ outf, int ldf,     // fp32 output (nullable)
         float* __restrict__ outt, int ldt)     // tf32-rounded output (nullable)
{
    __shared__ float As[BM * 36];
    __shared__ float Bs[128 * 36];
    const int m0 = blockIdx.x * BM;
    const int n0 = blockIdx.y * 128;
    const int tid = threadIdx.x;
    const int warp = tid >> 5, lane = tid & 31;
    const int wm = warp >> 2, wn = warp & 3;   // 2 x 4, warp tile (BM/2) x 32
    const int grp = lane >> 2, tig = lane & 3;
    constexpr int MS = BM / 32;

    float acc[MS][4][4];
#pragma unroll
    for (int i = 0; i < MS; i++)
#pragma unroll
        for (int j = 0; j < 4; j++)
#pragma unroll
            for (int k = 0; k < 4; k++) acc[i][j][k] = 0.f;

    for (int kt = 0; kt < HH / 32; kt++) {
        const int k0 = kt * 32;
        __syncthreads();
#pragma unroll
        for (int it = 0; it < BM / 32; it++) {
            int idx = tid + it * 256;
            int r = idx >> 3, v = idx & 7;
            *(float4*)(As + r * 36 + v * 4) =
                *(const float4*)(A + (size_t)(m0 + r) * HH + k0 + v * 4);
        }
#pragma unroll
        for (int it = 0; it < 4; it++) {
            int idx = tid + it * 256;
            int r = idx >> 3, v = idx & 7;
            *(float4*)(Bs + r * 36 + v * 4) =
                *(const float4*)(W + (size_t)(n0 + r) * HH + k0 + v * 4);
        }
        __syncthreads();
#pragma unroll
        for (int ks = 0; ks < 4; ks++) {
            uint32_t af[MS][4], bf[4][2];
#pragma unroll
            for (int ms = 0; ms < MS; ms++) {
                int r = wm * (BM / 2) + ms * 16 + grp;
                af[ms][0] = __float_as_uint(As[r * 36 + ks * 8 + tig]);
                af[ms][1] = __float_as_uint(As[(r + 8) * 36 + ks * 8 + tig]);
                af[ms][2] = __float_as_uint(As[r * 36 + ks * 8 + tig + 4]);
                af[ms][3] = __float_as_uint(As[(r + 8) * 36 + ks * 8 + tig + 4]);
            }
#pragma unroll
            for (int ns = 0; ns < 4; ns++) {
                int nb = wn * 32 + ns * 8 + grp;
                bf[ns][0] = __float_as_uint(Bs[nb * 36 + ks * 8 + tig]);
                bf[ns][1] = __float_as_uint(Bs[nb * 36 + ks * 8 + tig + 4]);
            }
#pragma unroll
            for (int ms = 0; ms < MS; ms++)
#pragma unroll
                for (int ns = 0; ns < 4; ns++)
                    mma8(acc[ms][ns], af[ms], bf[ns]);
        }
    }
#pragma unroll
    for (int ms = 0; ms < MS; ms++) {
#pragma unroll
        for (int ns = 0; ns < 4; ns++) {
            int rl = wm * (BM / 2) + ms * 16 + grp;
            int cl = wn * 32 + ns * 8 + tig * 2;
            float v0 = acc[ms][ns][0] + bias[n0 + cl];
            float v1 = acc[ms][ns][1] + bias[n0 + cl + 1];
            float v2 = acc[ms][ns][2] + bias[n0 + cl];
            float v3 = acc[ms][ns][3] + bias[n0 + cl + 1];
            int r0 = m0 + rl, r1 = m0 + rl + 8, cg = n0 + cl;
            if (outf) {
                outf[(size_t)r0 * ldf + cg]     = v0;
                outf[(size_t)r0 * ldf + cg + 1] = v1;
                outf[(size_t)r1 * ldf + cg]     = v2;
                outf[(size_t)r1 * ldf + cg + 1] = v3;
            }
            if (outt) {
                outt[(size_t)r0 * ldt + cg]     = to_tf32(v0);
                outt[(size_t)r0 * ldt + cg + 1] = to_tf32(v1);
                outt[(size_t)r1 * ldt + cg]     = to_tf32(v2);
                outt[(size_t)r1 * ldt + cg + 1] = to_tf32(v3);
            }
        }
    }
}

// ================= prep kernels =================
__global__ void k_prep_x(const float* __restrict__ x) {
    for (int idx = blockIdx.x * blockDim.x + threadIdx.x; idx < SEQ * BQ * IN;
         idx += gridDim.x * blockDim.x) {
        int i = idx % IN;
        int rem = idx / IN;
        int b = rem % BQ;
        int t = rem / BQ;
        g_xT[idx] = to_tf32(x[(size_t)(b * SEQ + t) * IN + i]);
    }
}

__global__ void k_prep_w(const float* __restrict__ wih, const float* __restrict__ whh,
                         const float* __restrict__ bih, const float* __restrict__ bhh,
                         float* __restrict__ Wo, float* __restrict__ bo) {
    for (int idx = blockIdx.x * blockDim.x + threadIdx.x; idx < G4 * KT;
         idx += gridDim.x * blockDim.x) {
        int n = idx / KT, k = idx % KT;
        float v = (k < IN) ? wih[(size_t)n * IN + k] : whh[(size_t)n * HH + (k - IN)];
        Wo[idx] = to_tf32(v);
        if (idx < G4) bo[idx] = bih[idx] + bhh[idx];
    }
}

__global__ void k_round(const float* __restrict__ s, float* __restrict__ d, int n) {
    for (int idx = blockIdx.x * blockDim.x + threadIdx.x; idx < n;
         idx += gridDim.x * blockDim.x)
        d[idx] = to_tf32(s[idx]);
}

__global__ void k_zero() {
    for (int idx = blockIdx.x * blockDim.x + threadIdx.x; idx < BQ * HH;
         idx += gridDim.x * blockDim.x) {
        g_hA[idx] = 0.f;
        g_c[idx] = 0.f;
        if (idx < BQ * OUTD) g_out[idx] = 0.f;
    }
}

// ================= launch =================
extern "C" void kernel_launch(void* const* d_in, const int* in_sizes, int n_in,
                              void* d_out, int out_size)
{
    const float* x     = (const float*)d_in[0];
    const float* Wih_e = (const float*)d_in[1];
    const float* Whh_e = (const float*)d_in[2];
    const float* bih_e = (const float*)d_in[3];
    const float* bhh_e = (const float*)d_in[4];
    const float* Wih_d = (const float*)d_in[5];
    const float* Whh_d = (const float*)d_in[6];
    const float* bih_d = (const float*)d_in[7];
    const float* bhh_d = (const float*)d_in[8];
    const float* Wfc   = (const float*)d_in[9];
    const float* bfc   = (const float*)d_in[10];
    const float* Wfcc  = (const float*)d_in[11];
    const float* bfcc  = (const float*)d_in[12];
    const float* Wout  = (const float*)d_in[13];
    const float* bout  = (const float*)d_in[14];
    float* out = (float*)d_out;

    float *p_xT, *p_We, *p_Wd, *p_Wfc, *p_Wfcc, *p_Wout, *p_be, *p_bd;
    float *p_hA, *p_hB, *p_c, *p_hdA, *p_hdB, *p_cd, *p_out;
    cudaGetSymbolAddress((void**)&p_xT, g_xT);
    cudaGetSymbolAddress((void**)&p_We, g_We);
    cudaGetSymbolAddress((void**)&p_Wd, g_Wd);
    cudaGetSymbolAddress((void**)&p_Wfc, g_Wfc);
    cudaGetSymbolAddress((void**)&p_Wfcc, g_Wfcc);
    cudaGetSymbolAddress((void**)&p_Wout, g_Wout);
    cudaGetSymbolAddress((void**)&p_be, g_be);
    cudaGetSymbolAddress((void**)&p_bd, g_bd);
    cudaGetSymbolAddress((void**)&p_hA, g_hA);
    cudaGetSymbolAddress((void**)&p_hB, g_hB);
    cudaGetSymbolAddress((void**)&p_c, g_c);
    cudaGetSymbolAddress((void**)&p_hdA, g_hdA);
    cudaGetSymbolAddress((void**)&p_hdB, g_hdB);
    cudaGetSymbolAddress((void**)&p_cd, g_cd);
    cudaGetSymbolAddress((void**)&p_out, g_out);

    const int smem = 128 * 264 * (int)sizeof(float);  // 135168 B
    cudaFuncSetAttribute(lstm_step, cudaFuncAttributeMaxDynamicSharedMemorySize, smem);

    // prep (runs every call: deterministic, idempotent)
    k_prep_x<<<2048, 256>>>(x);
    k_prep_w<<<2048, 256>>>(Wih_e, Whh_e, bih_e, bhh_e, p_We, p_be);
    k_prep_w<<<2048, 256>>>(Wih_d, Whh_d, bih_d, bhh_d, p_Wd, p_bd);
    k_round<<<1024, 256>>>(Wfc, p_Wfc, HH * HH);
    k_round<<<1024, 256>>>(Wfcc, p_Wfcc, HH * HH);
    k_round<<<256, 256>>>(Wout, p_Wout, OUTD * HH);
    k_zero<<<1024, 256>>>();

    // encoder: 96 steps, h ping-pong
    float* hb[2] = {p_hA, p_hB};
    dim3 gstep(8, 16);
    for (int t = 0; t < SEQ; t++)
        lstm_step<<<gstep, 256, smem>>>(p_xT + (size_t)t * BQ * IN, hb[t & 1],
                                        p_We, p_be, p_c, hb[(t + 1) & 1]);
    float* henc = hb[SEQ & 1];

    // bridge
    linear_k<128><<<dim3(8, 8), 256>>>(henc, p_Wfc, bfc, nullptr, 0, p_hdA, HH);
    linear_k<128><<<dim3(8, 8), 256>>>(henc, p_Wfcc, bfcc, p_cd, HH, nullptr, 0);

    // decoder: 24 steps (lstm + output projection)
    float* hd[2] = {p_hdA, p_hdB};
    for (int t = 0; t < HOR; t++) {
        lstm_step<<<gstep, 256, smem>>>(p_out, hd[t & 1], p_Wd, p_bd, p_cd,
                                        hd[(t + 1) & 1]);
        linear_k<64><<<dim3(16, 1), 256>>>(hd[(t + 1) & 1], p_Wout, bout,
                                           out + (size_t)t * OUTD, HOR * OUTD,
                                           p_out, OUTD);
    }
}